// round 9
// baseline (speedup 1.0000x reference)
#include <cuda_runtime.h>
#include <cstdint>

// Problem constants
#define NSAMP 32768     // 128*256
#define HID   100
#define G4    400
#define INPF  5
#define NPOS  62
#define NREG  16
#define MTILE 16        // samples per block
#define TM    8         // samples per thread
#define NP    (TM/2)    // f32x2 sample-pairs per thread (4)
#define YB    2         // blockDim.y  (YB*TM == MTILE)
#define NTHR  (100*YB)  // 200 threads
#define HSTRIDE 20      // row stride of h_sh in floats (80B, 16B-aligned)

__constant__ int c_len[NREG] = {5,5,2,2,6,6,5,5,5,2,2,5,3,3,3,3};
__constant__ int c_off[NREG] = {0,5,10,12,14,20,26,31,36,41,43,45,50,53,56,59};
__constant__ int c_idx[62] = {
    3,0,1,2,4,
    7,8,9,10,11,
    5,6,
    13,12,
    14,15,23,24,32,33,
    22,21,31,30,40,39,
    16,17,18,19,20,
    25,26,27,28,29,
    34,35,36,37,38,
    41,42,
    49,48,
    43,44,45,46,47,
    50,51,57,
    56,55,61,
    52,53,54,
    58,59,60
};

// Prepacked forward Whh: layout [r][k][j][g]  (g fastest, g in {i,f,g,o})
// element = w_hh[r][0][g*100+j][k]
__device__ float g_whhpack[NREG * HID * HID * 4];

// ---------- packed f32x2 helpers ----------
__device__ __forceinline__ unsigned long long pack2(float lo, float hi) {
    unsigned long long r;
    asm("mov.b64 %0, {%1, %2};" : "=l"(r) : "f"(lo), "f"(hi));
    return r;
}
__device__ __forceinline__ void unpack2(unsigned long long v, float& lo, float& hi) {
    asm("mov.b64 {%0, %1}, %2;" : "=f"(lo), "=f"(hi) : "l"(v));
}
__device__ __forceinline__ unsigned long long splat2(float v) {
    unsigned long long r;
    asm("mov.b64 %0, {%1, %1};" : "=l"(r) : "f"(v));
    return r;
}
__device__ __forceinline__ void fma2(unsigned long long& acc,
                                     unsigned long long a,
                                     unsigned long long b) {
    asm("fma.rn.f32x2 %0, %1, %2, %0;" : "+l"(acc) : "l"(a), "l"(b));
}

// ---------- activations (MUFU.TANH path) ----------
__device__ __forceinline__ float tanh_(float x) {
    float r;
    asm("tanh.approx.f32 %0, %1;" : "=f"(r) : "f"(x));
    return r;
}
__device__ __forceinline__ float sigm(float x) {
    return fmaf(0.5f, tanh_(0.5f * x), 0.5f);
}

// ---------- weight prepack ----------
__global__ void prepack_kernel(const float* __restrict__ w_hh) {
    int idx = blockIdx.x * blockDim.x + threadIdx.x;
    if (idx >= NREG * HID * HID * 4) return;
    int g = idx & 3;
    int j = (idx >> 2) % HID;
    int k = (idx / (4 * HID)) % HID;
    int r = idx / (4 * HID * HID);
    g_whhpack[idx] = w_hh[((size_t)(r * 2) * G4 + g * HID + j) * HID + k];
}

// ---------- main LSTM kernel ----------
// blockDim = (100, 2). Thread j owns gate rows {j, j+100, j+200, j+300}
// and hidden index j; processes TM=8 samples as NP=4 f32x2 sample-pairs.
// __launch_bounds__(200, 3): 3 independent CTAs per SM -> 18.75 warps and
// cross-CTA overlap of FMA (k-loop) and MUFU (pointwise) phases.
__global__ void __launch_bounds__(NTHR, 3) lstm_main(
    const float* __restrict__ feat,   // [32768, 62, 5]
    const float* __restrict__ w_ih,   // [16, 2, 400, 5]
    const float* __restrict__ b_ih,   // [16, 2, 400]
    const float* __restrict__ b_hh,   // [16, 2, 400]
    float* __restrict__ out)          // [32768, 16, 200]
{
    __shared__ float h_sh[2][HID][HSTRIDE];   // 16.0 KB, double-buffered
    __shared__ float x_sh[6][MTILE][INPF];    //  1.9 KB
    __shared__ float wi_sh[4][INPF][HID];     //  8.0 KB
    __shared__ float bi_sh[4][HID];           //  1.6 KB

    const int j   = threadIdx.x;          // 0..99
    const int y   = threadIdx.y;          // 0..YB-1
    const int tid = y * 100 + j;
    const int r   = blockIdx.y;
    const int m0  = blockIdx.x * MTILE;
    const int T   = c_len[r];
    const int off = c_off[r];
    const int mb  = y * TM;

    // Stage input features for this block's samples and region positions.
    for (int e = tid; e < T * MTILE * INPF; e += NTHR) {
        int t   = e / (MTILE * INPF);
        int rem = e - t * (MTILE * INPF);
        int m   = rem / INPF;
        int c   = rem - m * INPF;
        x_sh[t][m][c] =
            feat[((size_t)(m0 + m) * NPOS + c_idx[off + t]) * INPF + c];
    }

    // Stage forward-direction input weights + fused bias into smem.
    for (int e = tid; e < G4 * INPF; e += NTHR) {
        int row = e / INPF;               // 0..399  (= g*100 + jj)
        int c   = e - row * INPF;
        int g   = row / HID;
        int jj  = row - g * HID;
        wi_sh[g][c][jj] = __ldg(&w_ih[((size_t)(r * 2) * G4 + row) * INPF + c]);
    }
    for (int e = tid; e < G4; e += NTHR) {
        int g  = e / HID;
        int jj = e - g * HID;
        int row = (r * 2) * G4 + e;
        bi_sh[g][jj] = __ldg(&b_ih[row]) + __ldg(&b_hh[row]);
    }

    const float* wbase = g_whhpack + ((size_t)r * HID * HID + j) * 4;

    float creg[TM];
#pragma unroll
    for (int p = 0; p < TM; p++) creg[p] = 0.0f;

    __syncthreads();   // x_sh / wi_sh / bi_sh ready

    for (int t = 0; t < T; t++) {
        // acc[g][q] = {gate_g(sample mb+2q), gate_g(sample mb+2q+1)}
        unsigned long long acc[4][NP];
        {
            float wfi[4][5], bsf[4];
#pragma unroll
            for (int g = 0; g < 4; g++) {
#pragma unroll
                for (int c = 0; c < 5; c++) wfi[g][c] = wi_sh[g][c][j];
                bsf[g] = bi_sh[g][j];
            }
#pragma unroll
            for (int q = 0; q < NP; q++) {
                const float* xv0 = x_sh[t][mb + 2 * q];
                const float* xv1 = xv0 + INPF;
#pragma unroll
                for (int g = 0; g < 4; g++) {
                    float gv0 = bsf[g] + xv0[0]*wfi[g][0] + xv0[1]*wfi[g][1] + xv0[2]*wfi[g][2]
                                       + xv0[3]*wfi[g][3] + xv0[4]*wfi[g][4];
                    float gv1 = bsf[g] + xv1[0]*wfi[g][0] + xv1[1]*wfi[g][1] + xv1[2]*wfi[g][2]
                                       + xv1[3]*wfi[g][3] + xv1[4]*wfi[g][4];
                    acc[g][q] = pack2(gv0, gv1);
                }
            }
        }

        if (t > 0) {   // h == 0 at t == 0, skip the hh matvec entirely
            const float* hrow = &h_sh[t & 1][0][mb];
#pragma unroll 2
            for (int k = 0; k < HID; k++) {
                // one LDG.128: {w_i, w_f, w_g, w_o} at (k, j)
                float4 w = __ldg(
                    reinterpret_cast<const float4*>(wbase + (size_t)k * G4));
                unsigned long long ws[4];
                ws[0] = splat2(w.x); ws[1] = splat2(w.y);
                ws[2] = splat2(w.z); ws[3] = splat2(w.w);
                // two broadcast LDS.128: h for samples mb..mb+7 as 4 pairs
                const float* hk = hrow + k * HSTRIDE;
                ulonglong2 ha = *reinterpret_cast<const ulonglong2*>(hk);
                ulonglong2 hb = *reinterpret_cast<const ulonglong2*>(hk + 4);
                unsigned long long hp[NP] = {ha.x, ha.y, hb.x, hb.y};
#pragma unroll
                for (int g = 0; g < 4; g++) {
#pragma unroll
                    for (int q = 0; q < NP; q++)
                        fma2(acc[g][q], ws[g], hp[q]);
                }
            }
        }

        // LSTM pointwise (thread j owns hidden unit j); write h to other buffer
        float* hdst = &h_sh[(t + 1) & 1][j][mb];
#pragma unroll
        for (int q = 0; q < NP; q++) {
            float gi0, gi1, gf0, gf1, gg0, gg1, go0, go1;
            unpack2(acc[0][q], gi0, gi1);
            unpack2(acc[1][q], gf0, gf1);
            unpack2(acc[2][q], gg0, gg1);
            unpack2(acc[3][q], go0, go1);
            int p0 = 2 * q, p1 = 2 * q + 1;
            creg[p0] = sigm(gf0) * creg[p0] + sigm(gi0) * tanh_(gg0);
            creg[p1] = sigm(gf1) * creg[p1] + sigm(gi1) * tanh_(gg1);
            float h0 = sigm(go0) * tanh_(creg[p0]);
            float h1 = sigm(go1) * tanh_(creg[p1]);
            *reinterpret_cast<float2*>(hdst + p0) = make_float2(h0, h1);
        }
        __syncthreads();   // new h visible; old-buffer reads complete
    }

    // Write forward output h_f (re-read own row from final h buffer)
    {
        const float* hfin = &h_sh[T & 1][j][mb];
#pragma unroll
        for (int p = 0; p < TM; p++)
            out[(size_t)(m0 + mb + p) * (NREG * 200) + r * 200 + j] = hfin[p];
    }

    // "Backward" LSTM: single step from h=c=0 on the LAST position.
    float wbi[4][5];
    float bsb[4];
#pragma unroll
    for (int g = 0; g < 4; g++) {
        int row = (r * 2 + 1) * G4 + g * HID + j;   // d = 1
#pragma unroll
        for (int c = 0; c < 5; c++) wbi[g][c] = __ldg(&w_ih[(size_t)row * 5 + c]);
        bsb[g] = __ldg(&b_ih[row]) + __ldg(&b_hh[row]);
    }
#pragma unroll
    for (int p = 0; p < TM; p++) {
        const float* xv = x_sh[T - 1][mb + p];
        float x0 = xv[0], x1 = xv[1], x2 = xv[2], x3 = xv[3], x4 = xv[4];
        float gi = bsb[0] + x0*wbi[0][0] + x1*wbi[0][1] + x2*wbi[0][2] + x3*wbi[0][3] + x4*wbi[0][4];
        float gg = bsb[2] + x0*wbi[2][0] + x1*wbi[2][1] + x2*wbi[2][2] + x3*wbi[2][3] + x4*wbi[2][4];
        float go = bsb[3] + x0*wbi[3][0] + x1*wbi[3][1] + x2*wbi[3][2] + x3*wbi[3][3] + x4*wbi[3][4];
        float cb = sigm(gi) * tanh_(gg);
        float hb = sigm(go) * tanh_(cb);
        out[(size_t)(m0 + mb + p) * (NREG * 200) + r * 200 + HID + j] = hb;
    }
}

extern "C" void kernel_launch(void* const* d_in, const int* in_sizes, int n_in,
                              void* d_out, int out_size) {
    const float* feat = (const float*)d_in[0];
    const float* w_ih = (const float*)d_in[1];
    const float* w_hh = (const float*)d_in[2];
    const float* b_ih = (const float*)d_in[3];
    const float* b_hh = (const float*)d_in[4];
    float* out = (float*)d_out;

    int total = NREG * HID * HID * 4;
    prepack_kernel<<<(total + 255) / 256, 256>>>(w_hh);

    dim3 grid(NSAMP / MTILE, NREG);
    dim3 block(100, YB);
    lstm_main<<<grid, block>>>(feat, w_ih, b_ih, b_hh, out);
}

// round 11
// speedup vs baseline: 1.0113x; 1.0113x over previous
#include <cuda_runtime.h>
#include <cstdint>

// Problem constants
#define NSAMP 32768     // 128*256
#define HID   100
#define G4    400
#define INPF  5
#define NPOS  62
#define NREG  16
#define MTILE 32        // samples per block
#define TM    16        // samples per thread
#define NP    (TM/2)    // f32x2 sample-pairs per thread (8)
#define YB    2         // blockDim.y  (YB*TM == MTILE)
#define NTHR  (100*YB)  // 200 threads
#define HSTRIDE 36      // row stride of h_sh in floats (16B-aligned, bank-offset)

__constant__ int c_len[NREG] = {5,5,2,2,6,6,5,5,5,2,2,5,3,3,3,3};
__constant__ int c_off[NREG] = {0,5,10,12,14,20,26,31,36,41,43,45,50,53,56,59};
__constant__ int c_idx[62] = {
    3,0,1,2,4,
    7,8,9,10,11,
    5,6,
    13,12,
    14,15,23,24,32,33,
    22,21,31,30,40,39,
    16,17,18,19,20,
    25,26,27,28,29,
    34,35,36,37,38,
    41,42,
    49,48,
    43,44,45,46,47,
    50,51,57,
    56,55,61,
    52,53,54,
    58,59,60
};

// Prepacked forward Whh: layout [r][k][j][g]  (g fastest, g in {i,f,g,o})
// element = w_hh[r][0][g*100+j][k]
__device__ float g_whhpack[NREG * HID * HID * 4];

// ---------- packed f32x2 helpers ----------
__device__ __forceinline__ unsigned long long pack2(float lo, float hi) {
    unsigned long long r;
    asm("mov.b64 %0, {%1, %2};" : "=l"(r) : "f"(lo), "f"(hi));
    return r;
}
__device__ __forceinline__ void unpack2(unsigned long long v, float& lo, float& hi) {
    asm("mov.b64 {%0, %1}, %2;" : "=f"(lo), "=f"(hi) : "l"(v));
}
__device__ __forceinline__ unsigned long long splat2(float v) {
    unsigned long long r;
    asm("mov.b64 %0, {%1, %1};" : "=l"(r) : "f"(v));
    return r;
}
__device__ __forceinline__ void fma2(unsigned long long& acc,
                                     unsigned long long a,
                                     unsigned long long b) {
    asm("fma.rn.f32x2 %0, %1, %2, %0;" : "+l"(acc) : "l"(a), "l"(b));
}

// ---------- activations (MUFU.TANH path) ----------
__device__ __forceinline__ float tanh_(float x) {
    float r;
    asm("tanh.approx.f32 %0, %1;" : "=f"(r) : "f"(x));
    return r;
}
__device__ __forceinline__ float sigm(float x) {
    return fmaf(0.5f, tanh_(0.5f * x), 0.5f);
}

// ---------- weight prepack ----------
__global__ void prepack_kernel(const float* __restrict__ w_hh) {
    int idx = blockIdx.x * blockDim.x + threadIdx.x;
    if (idx >= NREG * HID * HID * 4) return;
    int g = idx & 3;
    int j = (idx >> 2) % HID;
    int k = (idx / (4 * HID)) % HID;
    int r = idx / (4 * HID * HID);
    g_whhpack[idx] = w_hh[((size_t)(r * 2) * G4 + g * HID + j) * HID + k];
}

// ---------- main LSTM kernel ----------
// blockDim = (100, 2). Thread j owns gate rows {j, j+100, j+200, j+300}
// and hidden index j; processes TM=16 samples as NP=8 f32x2 sample-pairs.
// 200-thread CTA, ~128 regs, 42KB smem -> 2 CTAs resident per SM; the two
// CTAs de-phase so one CTA's MUFU pointwise overlaps the other's FMA k-loop.
__global__ void __launch_bounds__(NTHR) lstm_main(
    const float* __restrict__ feat,   // [32768, 62, 5]
    const float* __restrict__ w_ih,   // [16, 2, 400, 5]
    const float* __restrict__ b_ih,   // [16, 2, 400]
    const float* __restrict__ b_hh,   // [16, 2, 400]
    float* __restrict__ out)          // [32768, 16, 200]
{
    __shared__ float h_sh[2][HID][HSTRIDE];   // 28.8 KB, double-buffered
    __shared__ float x_sh[6][MTILE][INPF];    //  3.8 KB
    __shared__ float wi_sh[4][INPF][HID];     //  8.0 KB
    __shared__ float bi_sh[4][HID];           //  1.6 KB

    const int j   = threadIdx.x;          // 0..99
    const int y   = threadIdx.y;          // 0..YB-1
    const int tid = y * 100 + j;
    const int r   = blockIdx.y;
    const int m0  = blockIdx.x * MTILE;
    const int T   = c_len[r];
    const int off = c_off[r];
    const int mb  = y * TM;

    // Stage input features for this block's samples and region positions.
    for (int e = tid; e < T * MTILE * INPF; e += NTHR) {
        int t   = e / (MTILE * INPF);
        int rem = e - t * (MTILE * INPF);
        int m   = rem / INPF;
        int c   = rem - m * INPF;
        x_sh[t][m][c] =
            feat[((size_t)(m0 + m) * NPOS + c_idx[off + t]) * INPF + c];
    }

    // Stage forward-direction input weights + fused bias into smem.
    for (int e = tid; e < G4 * INPF; e += NTHR) {
        int row = e / INPF;               // 0..399  (= g*100 + jj)
        int c   = e - row * INPF;
        int g   = row / HID;
        int jj  = row - g * HID;
        wi_sh[g][c][jj] = __ldg(&w_ih[((size_t)(r * 2) * G4 + row) * INPF + c]);
    }
    for (int e = tid; e < G4; e += NTHR) {
        int g  = e / HID;
        int jj = e - g * HID;
        int row = (r * 2) * G4 + e;
        bi_sh[g][jj] = __ldg(&b_ih[row]) + __ldg(&b_hh[row]);
    }

    const float* wbase = g_whhpack + ((size_t)r * HID * HID + j) * 4;

    float creg[TM];
#pragma unroll
    for (int p = 0; p < TM; p++) creg[p] = 0.0f;

    __syncthreads();   // x_sh / wi_sh / bi_sh ready

    for (int t = 0; t < T; t++) {
        // acc[g][q] = {gate_g(sample mb+2q), gate_g(sample mb+2q+1)}
        unsigned long long acc[4][NP];
        {
            float wfi[4][5], bsf[4];
#pragma unroll
            for (int g = 0; g < 4; g++) {
#pragma unroll
                for (int c = 0; c < 5; c++) wfi[g][c] = wi_sh[g][c][j];
                bsf[g] = bi_sh[g][j];
            }
#pragma unroll
            for (int q = 0; q < NP; q++) {
                const float* xv0 = x_sh[t][mb + 2 * q];
                const float* xv1 = xv0 + INPF;
#pragma unroll
                for (int g = 0; g < 4; g++) {
                    float gv0 = bsf[g] + xv0[0]*wfi[g][0] + xv0[1]*wfi[g][1] + xv0[2]*wfi[g][2]
                                       + xv0[3]*wfi[g][3] + xv0[4]*wfi[g][4];
                    float gv1 = bsf[g] + xv1[0]*wfi[g][0] + xv1[1]*wfi[g][1] + xv1[2]*wfi[g][2]
                                       + xv1[3]*wfi[g][3] + xv1[4]*wfi[g][4];
                    acc[g][q] = pack2(gv0, gv1);
                }
            }
        }

        if (t > 0) {   // h == 0 at t == 0, skip the hh matvec entirely
            const float* hrow = &h_sh[t & 1][0][mb];
#pragma unroll 2
            for (int k = 0; k < HID; k++) {
                // one LDG.128: {w_i, w_f, w_g, w_o} at (k, j)
                float4 w = __ldg(
                    reinterpret_cast<const float4*>(wbase + (size_t)k * G4));
                unsigned long long ws[4];
                ws[0] = splat2(w.x); ws[1] = splat2(w.y);
                ws[2] = splat2(w.z); ws[3] = splat2(w.w);
                // four broadcast LDS.128: h for samples mb..mb+15 as 8 pairs
                const float* hk = hrow + k * HSTRIDE;
                ulonglong2 ha = *reinterpret_cast<const ulonglong2*>(hk);
                ulonglong2 hb = *reinterpret_cast<const ulonglong2*>(hk + 4);
                ulonglong2 hc = *reinterpret_cast<const ulonglong2*>(hk + 8);
                ulonglong2 hd = *reinterpret_cast<const ulonglong2*>(hk + 12);
                unsigned long long hp[NP] = {ha.x, ha.y, hb.x, hb.y,
                                             hc.x, hc.y, hd.x, hd.y};
#pragma unroll
                for (int g = 0; g < 4; g++) {
#pragma unroll
                    for (int q = 0; q < NP; q++)
                        fma2(acc[g][q], ws[g], hp[q]);
                }
            }
        }

        // LSTM pointwise (thread j owns hidden unit j); write h to other buffer
        float* hdst = &h_sh[(t + 1) & 1][j][mb];
#pragma unroll
        for (int q = 0; q < NP; q++) {
            float gi0, gi1, gf0, gf1, gg0, gg1, go0, go1;
            unpack2(acc[0][q], gi0, gi1);
            unpack2(acc[1][q], gf0, gf1);
            unpack2(acc[2][q], gg0, gg1);
            unpack2(acc[3][q], go0, go1);
            int p0 = 2 * q, p1 = 2 * q + 1;
            creg[p0] = sigm(gf0) * creg[p0] + sigm(gi0) * tanh_(gg0);
            creg[p1] = sigm(gf1) * creg[p1] + sigm(gi1) * tanh_(gg1);
            float h0 = sigm(go0) * tanh_(creg[p0]);
            float h1 = sigm(go1) * tanh_(creg[p1]);
            *reinterpret_cast<float2*>(hdst + p0) = make_float2(h0, h1);
        }
        __syncthreads();   // new h visible; old-buffer reads complete
    }

    // Write forward output h_f (re-read own row from final h buffer)
    {
        const float* hfin = &h_sh[T & 1][j][mb];
#pragma unroll
        for (int p = 0; p < TM; p++)
            out[(size_t)(m0 + mb + p) * (NREG * 200) + r * 200 + j] = hfin[p];
    }

    // "Backward" LSTM: single step from h=c=0 on the LAST position.
    float wbi[4][5];
    float bsb[4];
#pragma unroll
    for (int g = 0; g < 4; g++) {
        int row = (r * 2 + 1) * G4 + g * HID + j;   // d = 1
#pragma unroll
        for (int c = 0; c < 5; c++) wbi[g][c] = __ldg(&w_ih[(size_t)row * 5 + c]);
        bsb[g] = __ldg(&b_ih[row]) + __ldg(&b_hh[row]);
    }
#pragma unroll
    for (int p = 0; p < TM; p++) {
        const float* xv = x_sh[T - 1][mb + p];
        float x0 = xv[0], x1 = xv[1], x2 = xv[2], x3 = xv[3], x4 = xv[4];
        float gi = bsb[0] + x0*wbi[0][0] + x1*wbi[0][1] + x2*wbi[0][2] + x3*wbi[0][3] + x4*wbi[0][4];
        float gg = bsb[2] + x0*wbi[2][0] + x1*wbi[2][1] + x2*wbi[2][2] + x3*wbi[2][3] + x4*wbi[2][4];
        float go = bsb[3] + x0*wbi[3][0] + x1*wbi[3][1] + x2*wbi[3][2] + x3*wbi[3][3] + x4*wbi[3][4];
        float cb = sigm(gi) * tanh_(gg);
        float hb = sigm(go) * tanh_(cb);
        out[(size_t)(m0 + mb + p) * (NREG * 200) + r * 200 + HID + j] = hb;
    }
}

extern "C" void kernel_launch(void* const* d_in, const int* in_sizes, int n_in,
                              void* d_out, int out_size) {
    const float* feat = (const float*)d_in[0];
    const float* w_ih = (const float*)d_in[1];
    const float* w_hh = (const float*)d_in[2];
    const float* b_ih = (const float*)d_in[3];
    const float* b_hh = (const float*)d_in[4];
    float* out = (float*)d_out;

    int total = NREG * HID * HID * 4;
    prepack_kernel<<<(total + 255) / 256, 256>>>(w_hh);

    dim3 grid(NSAMP / MTILE, NREG);
    dim3 block(100, YB);
    lstm_main<<<grid, block>>>(feat, w_ih, b_ih, b_hh, out);
}

// round 16
// speedup vs baseline: 2.5264x; 2.4981x over previous
#include <cuda_runtime.h>
#include <cuda_fp16.h>
#include <cstdint>

// Problem constants
#define NSAMP 32768
#define HID   100
#define G4    400
#define INPF  5
#define NPOS  62
#define NREG  16

#define MB     64          // samples per CTA
#define NTHR   512         // 16 warps: 2 m-groups x 8 n-groups
#define NPADC  448         // padded gate columns (56 n-tiles of 8)
#define KPADC  112         // K = h(100) | x(5) | bias(1) | zero(6)
#define KSTR   120         // row stride in halves (60 words = 28 mod 32: conflict-free)
#define B_HALF (NPADC * KSTR)        // 53760
#define A_HALF (MB * KSTR)           // 7680 per buffer
#define SMEM_BYTES ((B_HALF + 2 * A_HALF) * 2)   // 138240

__constant__ int c_len[NREG] = {5,5,2,2,6,6,5,5,5,2,2,5,3,3,3,3};
__constant__ int c_off[NREG] = {0,5,10,12,14,20,26,31,36,41,43,45,50,53,56,59};
__constant__ int c_idx[62] = {
    3,0,1,2,4,
    7,8,9,10,11,
    5,6,
    13,12,
    14,15,23,24,32,33,
    22,21,31,30,40,39,
    16,17,18,19,20,
    25,26,27,28,29,
    34,35,36,37,38,
    41,42,
    49,48,
    43,44,45,46,47,
    50,51,57,
    56,55,61,
    52,53,54,
    58,59,60
};

// Prepacked fp16 B: [r][n=448][k=120]; n = 4*j + gate (interleaved)
__device__ __align__(16) __half g_bpack[NREG * B_HALF];

// ---------- activations ----------
__device__ __forceinline__ float tanh_(float x) {
    float r; asm("tanh.approx.f32 %0, %1;" : "=f"(r) : "f"(x)); return r;
}
__device__ __forceinline__ float sigm(float x) {
    return fmaf(0.5f, tanh_(0.5f * x), 0.5f);
}

// ---------- fp16 m16n8k16 mma ----------
__device__ __forceinline__ void mma16816(float* d, const uint32_t* a,
                                         uint32_t b0, uint32_t b1) {
    asm volatile(
        "mma.sync.aligned.m16n8k16.row.col.f32.f16.f16.f32 "
        "{%0,%1,%2,%3}, {%4,%5,%6,%7}, {%8,%9}, {%0,%1,%2,%3};"
        : "+f"(d[0]), "+f"(d[1]), "+f"(d[2]), "+f"(d[3])
        : "r"(a[0]), "r"(a[1]), "r"(a[2]), "r"(a[3]), "r"(b0), "r"(b1));
}

// ---------- B prepack: fp32 weights -> interleaved fp16 [r][448][120] ----------
__global__ void prepack_b(const float* __restrict__ w_hh,
                          const float* __restrict__ w_ih,
                          const float* __restrict__ b_ih,
                          const float* __restrict__ b_hh) {
    int idx = blockIdx.x * blockDim.x + threadIdx.x;
    if (idx >= NREG * B_HALF) return;
    int r = idx / B_HALF;
    int rem = idx - r * B_HALF;
    int n = rem / KSTR;
    int k = rem - n * KSTR;
    float v = 0.0f;
    if (n < G4) {
        int gate = n & 3, j = n >> 2;
        int grow = gate * HID + j;
        if (k < HID)
            v = w_hh[((size_t)(r * 2) * G4 + grow) * HID + k];
        else if (k < HID + INPF)
            v = w_ih[((size_t)(r * 2) * G4 + grow) * INPF + (k - HID)];
        else if (k == HID + INPF)
            v = b_ih[(size_t)(r * 2) * G4 + grow] + b_hh[(size_t)(r * 2) * G4 + grow];
    }
    g_bpack[idx] = __float2half_rn(v);
}

// ---------- main kernel ----------
__global__ void __launch_bounds__(NTHR) rfl_kernel(
    const float* __restrict__ feat,   // [32768, 62, 5]
    const float* __restrict__ w_ih,   // [16, 2, 400, 5]
    const float* __restrict__ b_ih,   // [16, 2, 400]
    const float* __restrict__ b_hh,   // [16, 2, 400]
    float* __restrict__ out)          // [32768, 16, 200]
{
    extern __shared__ __half smh[];
    __half* B_sh = smh;                    // [448][120]
    __half* A_sh = smh + B_HALF;           // [2][64][120]

    const int tid  = threadIdx.x;
    const int w    = tid >> 5;
    const int lane = tid & 31;
    const int g    = lane >> 2;       // group 0..7
    const int tig  = lane & 3;        // thread-in-group
    const int mw   = w >> 3;          // m-half 0..1
    const int nw   = w & 7;           // n-group 0..7
    const int r    = blockIdx.y;
    const int m0   = blockIdx.x * MB;
    const int T    = c_len[r];
    const int off  = c_off[r];

    // ---- fill B from prepacked gmem (vectorized copy) ----
    {
        const uint4* src = reinterpret_cast<const uint4*>(g_bpack + (size_t)r * B_HALF);
        uint4* dst = reinterpret_cast<uint4*>(B_sh);
        for (int i = tid; i < B_HALF / 8; i += NTHR) dst[i] = src[i];
    }
    // ---- zero both A buffers ----
    {
        uint32_t* az = reinterpret_cast<uint32_t*>(A_sh);
        for (int i = tid; i < A_HALF; i += NTHR) az[i] = 0u;   // 2*A_HALF halves
    }
    __syncthreads();
    // bias col (both buffers) + x for t=0 (buffer 0)
    if (tid < 2 * MB) {
        int b = tid >> 6, m = tid & 63;
        A_sh[b * A_HALF + m * KSTR + 105] = __float2half_rn(1.0f);
    }
    for (int e = tid; e < MB * INPF; e += NTHR) {
        int m = e / INPF, c = e - m * INPF;
        A_sh[m * KSTR + 100 + c] = __float2half_rn(
            feat[((size_t)(m0 + m) * NPOS + c_idx[off]) * INPF + c]);
    }
    __syncthreads();

    float cst[2][7];
#pragma unroll
    for (int a = 0; a < 2; a++)
#pragma unroll
        for (int b = 0; b < 7; b++) cst[a][b] = 0.0f;

    for (int t = 0; t < T; t++) {
        const __half* Abuf = A_sh + (t & 1) * A_HALF;
        float acc[2][7][4];
#pragma unroll
        for (int mti = 0; mti < 2; mti++)
#pragma unroll
            for (int nt = 0; nt < 7; nt++)
#pragma unroll
                for (int u = 0; u < 4; u++) acc[mti][nt][u] = 0.0f;

#pragma unroll
        for (int kt = 0; kt < 7; kt++) {
            uint32_t af[2][4];
#pragma unroll
            for (int mti = 0; mti < 2; mti++) {
                int m = 32 * mw + 16 * mti + g;
                const __half* ap = Abuf + m * KSTR + kt * 16 + tig * 2;
                af[mti][0] = *reinterpret_cast<const uint32_t*>(ap);
                af[mti][1] = *reinterpret_cast<const uint32_t*>(ap + 8 * KSTR);
                af[mti][2] = *reinterpret_cast<const uint32_t*>(ap + 8);
                af[mti][3] = *reinterpret_cast<const uint32_t*>(ap + 8 * KSTR + 8);
            }
#pragma unroll
            for (int nt = 0; nt < 7; nt++) {
                int n = 8 * (7 * nw + nt) + g;
                const __half* bp = B_sh + n * KSTR + kt * 16 + tig * 2;
                uint32_t b0 = *reinterpret_cast<const uint32_t*>(bp);
                uint32_t b1 = *reinterpret_cast<const uint32_t*>(bp + 8);
                mma16816(acc[0][nt], af[0], b0, b1);
                mma16816(acc[1][nt], af[1], b0, b1);
            }
        }

        // ---- pointwise ----
        const bool last = (t == T - 1);
        __half* Anext = A_sh + ((t + 1) & 1) * A_HALF;
#pragma unroll
        for (int mti = 0; mti < 2; mti++) {
#pragma unroll
            for (int nt = 0; nt < 7; nt++) {
                float c0 = acc[mti][nt][0], c1 = acc[mti][nt][1];
                float c2 = acc[mti][nt][2], c3 = acc[mti][nt][3];
                float s0 = __shfl_xor_sync(0xffffffffu, c0, 1);
                float s1 = __shfl_xor_sync(0xffffffffu, c1, 1);
                float s2 = __shfl_xor_sync(0xffffffffu, c2, 1);
                float s3 = __shfl_xor_sync(0xffffffffu, c3, 1);
                // even tig: row g   with I=c0 F=c1 G=s0 O=s1
                // odd  tig: row g+8 with I=s2 F=s3 G=c2 O=c3
                bool odd = (tig & 1);
                float I = odd ? s2 : c0;
                float F = odd ? s3 : c1;
                float G = odd ? c2 : s0;
                float O = odd ? c3 : s1;
                float cc = sigm(F) * cst[mti][nt] + sigm(I) * tanh_(G);
                cst[mti][nt] = cc;
                float h = sigm(O) * tanh_(cc);
                int j = 2 * (7 * nw + nt) + (tig >> 1);
                int m = 32 * mw + 16 * mti + g + (odd ? 8 : 0);
                if (j < HID) {
                    Anext[m * KSTR + j] = __float2half_rn(h);
                    if (last)
                        out[(size_t)(m0 + m) * (NREG * 200) + r * 200 + j] = h;
                }
            }
        }

        // stage x for t+1 into the next buffer
        if (t + 1 < T) {
            for (int e = tid; e < MB * INPF; e += NTHR) {
                int m = e / INPF, c = e - m * INPF;
                Anext[m * KSTR + 100 + c] = __float2half_rn(
                    feat[((size_t)(m0 + m) * NPOS + c_idx[off + t + 1]) * INPF + c]);
            }
        }
        __syncthreads();
    }

    // ---- "Backward" LSTM: single step from h=c=0 on the LAST position ----
    for (int e = tid; e < MB * HID; e += NTHR) {
        int m = e / HID, j = e - (e / HID) * HID;
        const float* xv = feat + ((size_t)(m0 + m) * NPOS + c_idx[off + T - 1]) * INPF;
        float x0 = xv[0], x1 = xv[1], x2 = xv[2], x3 = xv[3], x4 = xv[4];
        size_t base = (size_t)(r * 2 + 1) * G4;
        int ri = j, rg = 200 + j, ro = 300 + j;
        const float* wv;
        wv = w_ih + (base + ri) * INPF;
        float gi = b_ih[base + ri] + b_hh[base + ri]
                 + x0*wv[0] + x1*wv[1] + x2*wv[2] + x3*wv[3] + x4*wv[4];
        wv = w_ih + (base + rg) * INPF;
        float gg = b_ih[base + rg] + b_hh[base + rg]
                 + x0*wv[0] + x1*wv[1] + x2*wv[2] + x3*wv[3] + x4*wv[4];
        wv = w_ih + (base + ro) * INPF;
        float go = b_ih[base + ro] + b_hh[base + ro]
                 + x0*wv[0] + x1*wv[1] + x2*wv[2] + x3*wv[3] + x4*wv[4];
        float cb = sigm(gi) * tanh_(gg);
        float hb = sigm(go) * tanh_(cb);
        out[(size_t)(m0 + m) * (NREG * 200) + r * 200 + HID + j] = hb;
    }
}

extern "C" void kernel_launch(void* const* d_in, const int* in_sizes, int n_in,
                              void* d_out, int out_size) {
    const float* feat = (const float*)d_in[0];
    const float* w_ih = (const float*)d_in[1];
    const float* w_hh = (const float*)d_in[2];
    const float* b_ih = (const float*)d_in[3];
    const float* b_hh = (const float*)d_in[4];
    float* out = (float*)d_out;

    static int smem_set = 0;
    if (!smem_set) {
        cudaFuncSetAttribute(rfl_kernel,
                             cudaFuncAttributeMaxDynamicSharedMemorySize,
                             SMEM_BYTES);
        smem_set = 1;
    }

    int total = NREG * B_HALF;
    prepack_b<<<(total + 255) / 256, 256>>>(w_hh, w_ih, b_ih, b_hh);

    dim3 grid(NSAMP / MB, NREG);
    rfl_kernel<<<grid, NTHR, SMEM_BYTES>>>(feat, w_ih, b_ih, b_hh, out);
}

// round 17
// speedup vs baseline: 2.5530x; 1.0105x over previous
#include <cuda_runtime.h>
#include <cuda_fp16.h>
#include <cstdint>

// Problem constants
#define NSAMP 32768
#define HID   100
#define G4    400
#define INPF  5
#define NPOS  62
#define NREG  16

#define MB     64          // samples per CTA
#define NTHR   512         // 16 warps: 2 m-groups x 8 n-groups
#define NPADC  448         // padded gate columns (56 n-tiles of 8)
#define KPADC  112         // K = h(100) | x(5) | bias(1) | zero(6)
#define KSTR   120         // row stride in halves (60 words = 28 mod 32: conflict-free)
#define B_HALF (NPADC * KSTR)        // 53760
#define A_HALF (MB * KSTR)           // 7680 per buffer
#define SMEM_BYTES ((B_HALF + 2 * A_HALF) * 2)   // 138240

__constant__ int c_len[NREG] = {5,5,2,2,6,6,5,5,5,2,2,5,3,3,3,3};
__constant__ int c_off[NREG] = {0,5,10,12,14,20,26,31,36,41,43,45,50,53,56,59};
__constant__ int c_idx[62] = {
    3,0,1,2,4,
    7,8,9,10,11,
    5,6,
    13,12,
    14,15,23,24,32,33,
    22,21,31,30,40,39,
    16,17,18,19,20,
    25,26,27,28,29,
    34,35,36,37,38,
    41,42,
    49,48,
    43,44,45,46,47,
    50,51,57,
    56,55,61,
    52,53,54,
    58,59,60
};

// Prepacked fp16 B: [r][n=448][k=120]; n = 4*j + gate (interleaved)
__device__ __align__(16) __half g_bpack[NREG * B_HALF];

// ---------- helpers ----------
__device__ __forceinline__ uint32_t smem_u32(const void* p) {
    uint32_t a;
    asm("{ .reg .u64 t; cvta.to.shared.u64 t, %1; cvt.u32.u64 %0, t; }"
        : "=r"(a) : "l"(p));
    return a;
}
__device__ __forceinline__ float tanh_(float x) {
    float r; asm("tanh.approx.f32 %0, %1;" : "=f"(r) : "f"(x)); return r;
}
__device__ __forceinline__ float sigm(float x) {
    return fmaf(0.5f, tanh_(0.5f * x), 0.5f);
}
__device__ __forceinline__ void mma16816(float* d, const uint32_t* a,
                                         uint32_t b0, uint32_t b1) {
    asm volatile(
        "mma.sync.aligned.m16n8k16.row.col.f32.f16.f16.f32 "
        "{%0,%1,%2,%3}, {%4,%5,%6,%7}, {%8,%9}, {%0,%1,%2,%3};"
        : "+f"(d[0]), "+f"(d[1]), "+f"(d[2]), "+f"(d[3])
        : "r"(a[0]), "r"(a[1]), "r"(a[2]), "r"(a[3]), "r"(b0), "r"(b1));
}
__device__ __forceinline__ void ldsm_x4(uint32_t& r0, uint32_t& r1,
                                        uint32_t& r2, uint32_t& r3, uint32_t ad) {
    asm volatile("ldmatrix.sync.aligned.m8n8.x4.shared.b16 {%0,%1,%2,%3}, [%4];"
                 : "=r"(r0), "=r"(r1), "=r"(r2), "=r"(r3) : "r"(ad));
}
__device__ __forceinline__ void ldsm_x2(uint32_t& r0, uint32_t& r1, uint32_t ad) {
    asm volatile("ldmatrix.sync.aligned.m8n8.x2.shared.b16 {%0,%1}, [%2];"
                 : "=r"(r0), "=r"(r1) : "r"(ad));
}

// ---------- B prepack: fp32 weights -> interleaved fp16 [r][448][120] ----------
__global__ void prepack_b(const float* __restrict__ w_hh,
                          const float* __restrict__ w_ih,
                          const float* __restrict__ b_ih,
                          const float* __restrict__ b_hh) {
    int idx = blockIdx.x * blockDim.x + threadIdx.x;
    if (idx >= NREG * B_HALF) return;
    int r = idx / B_HALF;
    int rem = idx - r * B_HALF;
    int n = rem / KSTR;
    int k = rem - n * KSTR;
    float v = 0.0f;
    if (n < G4) {
        int gate = n & 3, j = n >> 2;
        int grow = gate * HID + j;
        if (k < HID)
            v = w_hh[((size_t)(r * 2) * G4 + grow) * HID + k];
        else if (k < HID + INPF)
            v = w_ih[((size_t)(r * 2) * G4 + grow) * INPF + (k - HID)];
        else if (k == HID + INPF)
            v = b_ih[(size_t)(r * 2) * G4 + grow] + b_hh[(size_t)(r * 2) * G4 + grow];
    }
    g_bpack[idx] = __float2half_rn(v);
}

// ---------- main kernel ----------
__global__ void __launch_bounds__(NTHR) rfl_kernel(
    const float* __restrict__ feat,   // [32768, 62, 5]
    const float* __restrict__ w_ih,   // [16, 2, 400, 5]
    const float* __restrict__ b_ih,   // [16, 2, 400]
    const float* __restrict__ b_hh,   // [16, 2, 400]
    float* __restrict__ out)          // [32768, 16, 200]
{
    extern __shared__ __half smh[];
    __half* B_sh = smh;                    // [448][120]
    __half* A_sh = smh + B_HALF;           // [2][64][120]

    const int tid  = threadIdx.x;
    const int w    = tid >> 5;
    const int lane = tid & 31;
    const int g    = lane >> 2;       // group 0..7
    const int tig  = lane & 3;        // thread-in-group
    const int mw   = w >> 3;          // m-half 0..1
    const int nw   = w & 7;           // n-group 0..7
    const int r    = blockIdx.y;
    const int m0   = blockIdx.x * MB;
    const int T    = c_len[r];
    const int off  = c_off[r];

    // ---- fill B from prepacked gmem (vectorized copy) ----
    {
        const uint4* src = reinterpret_cast<const uint4*>(g_bpack + (size_t)r * B_HALF);
        uint4* dst = reinterpret_cast<uint4*>(B_sh);
        for (int i = tid; i < B_HALF / 8; i += NTHR) dst[i] = src[i];
    }
    // ---- zero both A buffers ----
    {
        uint32_t* az = reinterpret_cast<uint32_t*>(A_sh);
        for (int i = tid; i < A_HALF; i += NTHR) az[i] = 0u;   // 2*A_HALF halves
    }
    __syncthreads();
    // bias col (both buffers) + x for t=0 (buffer 0)
    if (tid < 2 * MB) {
        int b = tid >> 6, m = tid & 63;
        A_sh[b * A_HALF + m * KSTR + 105] = __float2half_rn(1.0f);
    }
    for (int e = tid; e < MB * INPF; e += NTHR) {
        int m = e / INPF, c = e - m * INPF;
        A_sh[m * KSTR + 100 + c] = __float2half_rn(
            feat[((size_t)(m0 + m) * NPOS + c_idx[off]) * INPF + c]);
    }
    __syncthreads();

    // ---- precompute ldmatrix lane addresses (byte offsets in shared space) ----
    // A (per mti): lanes 0-15 -> row (m_base+lane), col 0; lanes 16-31 -> row (lane-16), col 8
    const uint32_t A0_sm = smem_u32(A_sh);
    const uint32_t B0_sm = smem_u32(B_sh);
    uint32_t aAddr[2];
    {
        int rl = lane & 15;
        int cl = (lane >> 4) * 8;
#pragma unroll
        for (int mti = 0; mti < 2; mti++) {
            int m = 32 * mw + 16 * mti + rl;
            aAddr[mti] = A0_sm + (uint32_t)(m * KSTR + cl) * 2u;
        }
    }
    // B x4 groups i=0..2 cover n-tiles (2i, 2i+1); x2 group covers tile 6.
    // lanes 0-7: row L, col 0 | 8-15: row L-8, col 8 | 16-23: row 8+(L-16), col 0 | 24-31: row 8+(L-24), col 8
    uint32_t bAddr[4];
    {
        int rl = ((lane >> 4) & 1) * 8 + (lane & 7);
        int cl = (lane & 8) ? 8 : 0;
        int n0 = 8 * (7 * nw);
#pragma unroll
        for (int i = 0; i < 3; i++)
            bAddr[i] = B0_sm + (uint32_t)((n0 + 16 * i + rl) * KSTR + cl) * 2u;
        int rl2 = lane & 7;   // x2: lanes 0-15 used
        bAddr[3] = B0_sm + (uint32_t)((n0 + 48 + rl2) * KSTR + cl) * 2u;
    }

    float cst[2][7];
#pragma unroll
    for (int a = 0; a < 2; a++)
#pragma unroll
        for (int b = 0; b < 7; b++) cst[a][b] = 0.0f;

    for (int t = 0; t < T; t++) {
        const uint32_t abuf = (uint32_t)((t & 1) * A_HALF * 2);
        float acc[2][7][4];
#pragma unroll
        for (int mti = 0; mti < 2; mti++)
#pragma unroll
            for (int nt = 0; nt < 7; nt++)
#pragma unroll
                for (int u = 0; u < 4; u++) acc[mti][nt][u] = 0.0f;

#pragma unroll
        for (int kt = 0; kt < 7; kt++) {
            const uint32_t ko = (uint32_t)(kt * 32);
            uint32_t af[2][4];
            ldsm_x4(af[0][0], af[0][1], af[0][2], af[0][3], aAddr[0] + abuf + ko);
            ldsm_x4(af[1][0], af[1][1], af[1][2], af[1][3], aAddr[1] + abuf + ko);
            uint32_t bf[14];
            ldsm_x4(bf[0],  bf[1],  bf[2],  bf[3],  bAddr[0] + ko);
            ldsm_x4(bf[4],  bf[5],  bf[6],  bf[7],  bAddr[1] + ko);
            ldsm_x4(bf[8],  bf[9],  bf[10], bf[11], bAddr[2] + ko);
            ldsm_x2(bf[12], bf[13], bAddr[3] + ko);
#pragma unroll
            for (int nt = 0; nt < 7; nt++) {
                mma16816(acc[0][nt], af[0], bf[2 * nt], bf[2 * nt + 1]);
                mma16816(acc[1][nt], af[1], bf[2 * nt], bf[2 * nt + 1]);
            }
        }

        // ---- pointwise ----
        const bool last = (t == T - 1);
        __half* Anext = A_sh + ((t + 1) & 1) * A_HALF;
#pragma unroll
        for (int mti = 0; mti < 2; mti++) {
#pragma unroll
            for (int nt = 0; nt < 7; nt++) {
                float c0 = acc[mti][nt][0], c1 = acc[mti][nt][1];
                float c2 = acc[mti][nt][2], c3 = acc[mti][nt][3];
                float s0 = __shfl_xor_sync(0xffffffffu, c0, 1);
                float s1 = __shfl_xor_sync(0xffffffffu, c1, 1);
                float s2 = __shfl_xor_sync(0xffffffffu, c2, 1);
                float s3 = __shfl_xor_sync(0xffffffffu, c3, 1);
                // even tig: row g   with I=c0 F=c1 G=s0 O=s1
                // odd  tig: row g+8 with I=s2 F=s3 G=c2 O=c3
                bool odd = (tig & 1);
                float I = odd ? s2 : c0;
                float F = odd ? s3 : c1;
                float G = odd ? c2 : s0;
                float O = odd ? c3 : s1;
                float cc = sigm(F) * cst[mti][nt] + sigm(I) * tanh_(G);
                cst[mti][nt] = cc;
                float h = sigm(O) * tanh_(cc);
                int j = 2 * (7 * nw + nt) + (tig >> 1);
                int m = 32 * mw + 16 * mti + g + (odd ? 8 : 0);
                if (j < HID) {
                    Anext[m * KSTR + j] = __float2half_rn(h);
                    if (last)
                        out[(size_t)(m0 + m) * (NREG * 200) + r * 200 + j] = h;
                }
            }
        }

        // stage x for t+1 into the next buffer
        if (t + 1 < T) {
            for (int e = tid; e < MB * INPF; e += NTHR) {
                int m = e / INPF, c = e - m * INPF;
                Anext[m * KSTR + 100 + c] = __float2half_rn(
                    feat[((size_t)(m0 + m) * NPOS + c_idx[off + t + 1]) * INPF + c]);
            }
        }
        __syncthreads();
    }

    // ---- "Backward" LSTM: single step from h=c=0 on the LAST position ----
    for (int e = tid; e < MB * HID; e += NTHR) {
        int m = e / HID, j = e - (e / HID) * HID;
        const float* xv = feat + ((size_t)(m0 + m) * NPOS + c_idx[off + T - 1]) * INPF;
        float x0 = xv[0], x1 = xv[1], x2 = xv[2], x3 = xv[3], x4 = xv[4];
        size_t base = (size_t)(r * 2 + 1) * G4;
        int ri = j, rg = 200 + j, ro = 300 + j;
        const float* wv;
        wv = w_ih + (base + ri) * INPF;
        float gi = b_ih[base + ri] + b_hh[base + ri]
                 + x0*wv[0] + x1*wv[1] + x2*wv[2] + x3*wv[3] + x4*wv[4];
        wv = w_ih + (base + rg) * INPF;
        float gg = b_ih[base + rg] + b_hh[base + rg]
                 + x0*wv[0] + x1*wv[1] + x2*wv[2] + x3*wv[3] + x4*wv[4];
        wv = w_ih + (base + ro) * INPF;
        float go = b_ih[base + ro] + b_hh[base + ro]
                 + x0*wv[0] + x1*wv[1] + x2*wv[2] + x3*wv[3] + x4*wv[4];
        float cb = sigm(gi) * tanh_(gg);
        float hb = sigm(go) * tanh_(cb);
        out[(size_t)(m0 + m) * (NREG * 200) + r * 200 + HID + j] = hb;
    }
}

extern "C" void kernel_launch(void* const* d_in, const int* in_sizes, int n_in,
                              void* d_out, int out_size) {
    const float* feat = (const float*)d_in[0];
    const float* w_ih = (const float*)d_in[1];
    const float* w_hh = (const float*)d_in[2];
    const float* b_ih = (const float*)d_in[3];
    const float* b_hh = (const float*)d_in[4];
    float* out = (float*)d_out;

    static int smem_set = 0;
    if (!smem_set) {
        cudaFuncSetAttribute(rfl_kernel,
                             cudaFuncAttributeMaxDynamicSharedMemorySize,
                             SMEM_BYTES);
        smem_set = 1;
    }

    int total = NREG * B_HALF;
    prepack_b<<<(total + 255) / 256, 256>>>(w_hh, w_ih, b_ih, b_hh);

    dim3 grid(NSAMP / MB, NREG);
    rfl_kernel<<<grid, NTHR, SMEM_BYTES>>>(feat, w_ih, b_ih, b_hh, out);
}